// round 5
// baseline (speedup 1.0000x reference)
#include <cuda_runtime.h>
#include <cuda_bf16.h>
#include <math.h>

// Problem constants
#define B_  2
#define S_  2048
#define D_  2048
#define H_  16
#define HD_ 128
#define M_  (B_ * S_)              // 4096
#define TOT_ (B_ * H_ * S_ * HD_)  // 8388608

typedef unsigned long long u64;

// ---------------------------------------------------------------------------
// f32x2 packed-math + cp.async helpers (sm_100 family, non-'a')
// ---------------------------------------------------------------------------
__device__ __forceinline__ void ffma2(u64& d, u64 a, u64 b) {
    asm("fma.rn.f32x2 %0, %1, %2, %0;" : "+l"(d) : "l"(a), "l"(b));
}
__device__ __forceinline__ void fmul2(u64& d, u64 a) {
    asm("mul.rn.f32x2 %0, %0, %1;" : "+l"(d) : "l"(a));
}
__device__ __forceinline__ u64 pk2(float x, float y) {
    u64 r;
    asm("mov.b64 %0, {%1, %2};" : "=l"(r) : "f"(x), "f"(y));
    return r;
}
__device__ __forceinline__ void upk2(u64 v, float& x, float& y) {
    asm("mov.b64 {%0, %1}, %2;" : "=f"(x), "=f"(y) : "l"(v));
}
__device__ __forceinline__ unsigned smem_u32(const void* p) {
    unsigned a;
    asm("{ .reg .u64 t; cvta.to.shared.u64 t, %1; cvt.u32.u64 %0, t; }"
        : "=r"(a) : "l"(p));
    return a;
}
__device__ __forceinline__ void cp16(unsigned dst, const void* src) {
    asm volatile("cp.async.cg.shared.global [%0], [%1], 16;" :: "r"(dst), "l"(src));
}
#define CP_COMMIT() asm volatile("cp.async.commit_group;" ::: "memory")
#define CP_WAIT(n)  asm volatile("cp.async.wait_group %0;" :: "n"(n) : "memory")

// ---------------------------------------------------------------------------
// Scratch (no cudaMalloc allowed)
// ---------------------------------------------------------------------------
__device__ float g_xT [(size_t)D_ * M_];
__device__ float g_wqT[(size_t)D_ * D_];
__device__ float g_wkT[(size_t)D_ * D_];
__device__ float g_wvT[(size_t)D_ * D_];
__device__ float g_woT[(size_t)D_ * D_];
__device__ float g_qraw[(size_t)M_ * D_];
__device__ float g_kraw[(size_t)M_ * D_];
__device__ float g_vraw[(size_t)M_ * D_];
__device__ float g_Q[(size_t)TOT_];
__device__ float g_K[(size_t)TOT_];
__device__ float g_V[(size_t)TOT_];
__device__ float g_O[(size_t)TOT_];
__device__ float g_OtT[(size_t)D_ * M_];
__device__ float g_invf[64];

// ---------------------------------------------------------------------------
// 32x32 tiled transpose: in [R][C] -> out [C][R]
// ---------------------------------------------------------------------------
__global__ void transpose32(const float* __restrict__ in, float* __restrict__ out,
                            int R, int C)
{
    __shared__ float tile[32][33];
    const int bx = blockIdx.x * 32;   // col tile
    const int by = blockIdx.y * 32;   // row tile
    const int tx = threadIdx.x, ty = threadIdx.y;
#pragma unroll
    for (int j = 0; j < 4; j++)
        tile[ty + j * 8][tx] = in[(size_t)(by + ty + j * 8) * C + bx + tx];
    __syncthreads();
#pragma unroll
    for (int j = 0; j < 4; j++)
        out[(size_t)(bx + ty + j * 8) * R + by + tx] = tile[tx][ty + j * 8];
}

// ---------------------------------------------------------------------------
// GEMM (TN, FFMA2): C[M,N] = At^T @ Bt  with At [K][M], Bt [K][N] (both
// K-major). 128x128 tile, BK=16, 256 threads, 2 CTAs/SM.
// A stored value-duplicated in smem ((v,v) pairs) -> no pk2 in inner loop.
// B loaded by cp.async. z selects among 3 (B, C) pairs for fused QKV.
// ---------------------------------------------------------------------------
#define BK 16
#define ADROW 264          // 2*128 + 8 pad (floats)
#define BSROW 132          // 128 + 4 pad
#define SMEMG ((2 * BK * ADROW + 2 * BK * BSROW) * 4)

__global__ void __launch_bounds__(256, 2)
gemm3(const float* __restrict__ At,
      const float* __restrict__ B0t, const float* __restrict__ B1t,
      const float* __restrict__ B2t,
      float* __restrict__ C0, float* __restrict__ C1, float* __restrict__ C2,
      int Mdim, int Ndim, int Kdim)
{
    extern __shared__ float smem[];
    float* Ad  = smem;                      // [2][BK][ADROW]
    float* Bsm = smem + 2 * BK * ADROW;     // [2][BK][BSROW]
    const unsigned sbB = smem_u32(Bsm);

    const float* Bt;
    float* C;
    if (blockIdx.z == 0)      { Bt = B0t; C = C0; }
    else if (blockIdx.z == 1) { Bt = B1t; C = C1; }
    else                      { Bt = B2t; C = C2; }

    const int tid = threadIdx.x;
    const int tx = tid & 15;
    const int ty = tid >> 4;
    const int m0 = blockIdx.y * 128;
    const int n0 = blockIdx.x * 128;
    const int nt = Kdim / BK;

    // per-thread load slots: c = tid + i*256, k = c>>5, e4 = (c&31)*4
    const int k_0 = tid >> 5,         e4_0 = (tid & 31) * 4;
    const int k_1 = (tid + 256) >> 5, e4_1 = (tid & 31) * 4;

    float4 ra0, ra1;

#define LDGA(kt) do { \
        ra0 = *(const float4*)&At[(size_t)((kt) * BK + k_0) * Mdim + m0 + e4_0]; \
        ra1 = *(const float4*)&At[(size_t)((kt) * BK + k_1) * Mdim + m0 + e4_1]; \
    } while (0)

#define STSA(st) do { \
        ulonglong2* d0 = (ulonglong2*)&Ad[((st) * BK + k_0) * ADROW + 2 * e4_0]; \
        d0[0] = make_ulonglong2(pk2(ra0.x, ra0.x), pk2(ra0.y, ra0.y)); \
        d0[1] = make_ulonglong2(pk2(ra0.z, ra0.z), pk2(ra0.w, ra0.w)); \
        ulonglong2* d1 = (ulonglong2*)&Ad[((st) * BK + k_1) * ADROW + 2 * e4_1]; \
        d1[0] = make_ulonglong2(pk2(ra1.x, ra1.x), pk2(ra1.y, ra1.y)); \
        d1[1] = make_ulonglong2(pk2(ra1.z, ra1.z), pk2(ra1.w, ra1.w)); \
    } while (0)

#define CPB(kt, st) do { \
        cp16(sbB + (((st) * BK + k_0) * BSROW + e4_0) * 4, \
             &Bt[(size_t)((kt) * BK + k_0) * Ndim + n0 + e4_0]); \
        cp16(sbB + (((st) * BK + k_1) * BSROW + e4_1) * 4, \
             &Bt[(size_t)((kt) * BK + k_1) * Ndim + n0 + e4_1]); \
    } while (0)

    // prologue
    LDGA(0);
    CPB(0, 0); CP_COMMIT();
    STSA(0);
    LDGA(1);
    CPB(1, 1); CP_COMMIT();
    CP_WAIT(1);
    __syncthreads();

    u64 acc2[8][4];
#pragma unroll
    for (int i = 0; i < 8; i++)
#pragma unroll
        for (int j = 0; j < 4; j++) acc2[i][j] = 0ull;

    for (int t = 0; t < nt; t++) {
        const int buf = t & 1;
        const float* AdB = Ad + buf * BK * ADROW;
        const float* BsB = Bsm + buf * BK * BSROW;

#pragma unroll
        for (int kk = 0; kk < BK; kk++) {
            const ulonglong2* ar = (const ulonglong2*)&AdB[kk * ADROW + ty * 16];
            ulonglong2 a01 = ar[0], a23 = ar[1], a45 = ar[2], a67 = ar[3];
            u64 ad[8] = {a01.x, a01.y, a23.x, a23.y, a45.x, a45.y, a67.x, a67.y};
            const ulonglong2* br = (const ulonglong2*)&BsB[kk * BSROW + tx * 8];
            ulonglong2 b01 = br[0], b23 = br[1];
            u64 bp[4] = {b01.x, b01.y, b23.x, b23.y};
#pragma unroll
            for (int i = 0; i < 8; i++)
#pragma unroll
                for (int j = 0; j < 4; j++)
                    ffma2(acc2[i][j], ad[i], bp[j]);
        }
        __syncthreads();

        if (t + 1 < nt) {
            STSA(buf ^ 1);                       // stage t+1 A into other buf
            if (t + 2 < nt) {
                LDGA(t + 2);
                CPB(t + 2, buf); CP_COMMIT();
                CP_WAIT(1);                      // stage t+1 B complete
            } else {
                CP_WAIT(0);
            }
            __syncthreads();
        }
    }

    // epilogue
#pragma unroll
    for (int i = 0; i < 8; i++) {
        float c0, c1, c2, c3, c4, c5, c6, c7;
        upk2(acc2[i][0], c0, c1); upk2(acc2[i][1], c2, c3);
        upk2(acc2[i][2], c4, c5); upk2(acc2[i][3], c6, c7);
        size_t r = (size_t)(m0 + ty * 8 + i) * Ndim + n0 + tx * 8;
        *(float4*)&C[r]     = make_float4(c0, c1, c2, c3);
        *(float4*)&C[r + 4] = make_float4(c4, c5, c6, c7);
    }
#undef LDGA
#undef STSA
#undef CPB
}

// ---------------------------------------------------------------------------
// RoPE table (fp64 accuracy, tiny)
// ---------------------------------------------------------------------------
__global__ void init_rope()
{
    int j = threadIdx.x;
    if (j < 64) g_invf[j] = (float)exp(-(double)j * 0.14391156831212788);
}

// ---------------------------------------------------------------------------
// RoPE + pack [B,S,H*hd] -> [B,H,S,hd]
// ---------------------------------------------------------------------------
__global__ void rope_pack(const float* __restrict__ qraw,
                          const float* __restrict__ kraw,
                          const float* __restrict__ vraw,
                          float* __restrict__ Q, float* __restrict__ K,
                          float* __restrict__ V)
{
    int i = blockIdx.x * 256 + threadIdx.x;
    if (i >= TOT_) return;
    int d = i & (HD_ - 1);
    int s = (i >> 7) & (S_ - 1);
    int h = (i >> 18) & (H_ - 1);
    int b = i >> 22;

    size_t raw = (size_t)(b * S_ + s) * D_ + h * HD_ + d;
    int dp = (d < 64) ? d + 64 : d - 64;
    size_t rawp = raw + (dp - d);

    float inv = g_invf[d & 63];
    float ang = (float)s * inv;
    float sn, cs;
    sincosf(ang, &sn, &cs);

    float qv = qraw[raw], qp = qraw[rawp];
    float kv = kraw[raw], kp = kraw[rawp];
    float rq = (d < 64) ? -qp : qp;
    float rk = (d < 64) ? -kp : kp;

    Q[i] = fmaf(rq, sn, qv * cs);
    K[i] = fmaf(rk, sn, kv * cs);
    V[i] = vraw[raw];
}

// ---------------------------------------------------------------------------
// Flash attention, fp32 + FFMA2 inner loops, causal (unchanged from R4).
// ---------------------------------------------------------------------------
struct SmemAttn {
    float Qs[128][68];
    float Ks[128][68];
    float Vs[64][128];
    float Ss[64][68];
    float mrow[64];
    float lrow[64];
    float corr[64];
};

__global__ void __launch_bounds__(256)
flash_attn(const float* __restrict__ Qg, const float* __restrict__ Kg,
           const float* __restrict__ Vg, float* __restrict__ Og)
{
    extern __shared__ char smem_raw[];
    SmemAttn& sm = *reinterpret_cast<SmemAttn*>(smem_raw);

    const int tid = threadIdx.x;
    const int tx = tid & 15;
    const int ty = tid >> 4;
    const int bh = blockIdx.y;
    const int q0 = (gridDim.x - 1 - blockIdx.x) * 64;

    const float* Qb = Qg + (size_t)bh * S_ * HD_;
    const float* Kb = Kg + (size_t)bh * S_ * HD_;
    const float* Vb = Vg + (size_t)bh * S_ * HD_;
    float* Ob       = Og + (size_t)bh * S_ * HD_;

    const float scale = 0.08838834764831845f;

    for (int i = tid; i < 64 * 32; i += 256) {
        int r = i >> 5;
        int c4 = (i & 31) * 4;
        float4 v = *(const float4*)&Qb[(size_t)(q0 + r) * HD_ + c4];
        sm.Qs[c4 + 0][r] = v.x * scale;
        sm.Qs[c4 + 1][r] = v.y * scale;
        sm.Qs[c4 + 2][r] = v.z * scale;
        sm.Qs[c4 + 3][r] = v.w * scale;
    }
    if (tid < 64) {
        sm.mrow[tid] = -1e30f;
        sm.lrow[tid] = 0.f;
    }

    u64 o2[4][4];
#pragma unroll
    for (int i = 0; i < 4; i++)
#pragma unroll
        for (int j = 0; j < 4; j++) o2[i][j] = 0ull;

    const int ntiles = q0 / 64 + 1;
    for (int kt = 0; kt < ntiles; kt++) {
        const int k0 = kt * 64;

        for (int i = tid; i < 64 * 32; i += 256) {
            int c = i >> 5;
            int c4 = (i & 31) * 4;
            float4 kv4 = *(const float4*)&Kb[(size_t)(k0 + c) * HD_ + c4];
            sm.Ks[c4 + 0][c] = kv4.x;
            sm.Ks[c4 + 1][c] = kv4.y;
            sm.Ks[c4 + 2][c] = kv4.z;
            sm.Ks[c4 + 3][c] = kv4.w;
            float4 vv4 = *(const float4*)&Vb[(size_t)(k0 + c) * HD_ + c4];
            *(float4*)&sm.Vs[c][c4] = vv4;
        }
        __syncthreads();

        u64 sc2[4][2];
#pragma unroll
        for (int i = 0; i < 4; i++) { sc2[i][0] = 0ull; sc2[i][1] = 0ull; }

#pragma unroll 4
        for (int k = 0; k < 128; k++) {
            float4 qa = *(const float4*)&sm.Qs[k][ty * 4];
            ulonglong2 kp = *(const ulonglong2*)&sm.Ks[k][tx * 4];
            u64 qd[4];
            qd[0] = pk2(qa.x, qa.x); qd[1] = pk2(qa.y, qa.y);
            qd[2] = pk2(qa.z, qa.z); qd[3] = pk2(qa.w, qa.w);
#pragma unroll
            for (int i = 0; i < 4; i++) {
                ffma2(sc2[i][0], qd[i], kp.x);
                ffma2(sc2[i][1], qd[i], kp.y);
            }
        }
#pragma unroll
        for (int i = 0; i < 4; i++) {
            int gq = q0 + ty * 4 + i;
            float s0, s1, s2, s3;
            upk2(sc2[i][0], s0, s1);
            upk2(sc2[i][1], s2, s3);
            int gk = k0 + tx * 4;
            sm.Ss[ty * 4 + i][tx * 4 + 0] = (gk + 0 <= gq) ? s0 : -1e30f;
            sm.Ss[ty * 4 + i][tx * 4 + 1] = (gk + 1 <= gq) ? s1 : -1e30f;
            sm.Ss[ty * 4 + i][tx * 4 + 2] = (gk + 2 <= gq) ? s2 : -1e30f;
            sm.Ss[ty * 4 + i][tx * 4 + 3] = (gk + 3 <= gq) ? s3 : -1e30f;
        }
        __syncthreads();

        {
            int r = tid >> 2;
            int q = tid & 3;
            float mx = -1e30f;
#pragma unroll
            for (int cc = 0; cc < 16; cc++)
                mx = fmaxf(mx, sm.Ss[r][q * 16 + cc]);
            mx = fmaxf(mx, __shfl_xor_sync(0xffffffffu, mx, 1));
            mx = fmaxf(mx, __shfl_xor_sync(0xffffffffu, mx, 2));
            float m_old = sm.mrow[r];
            float m_new = fmaxf(m_old, mx);
            float ssum = 0.f;
#pragma unroll
            for (int cc = 0; cc < 16; cc++) {
                float p = __expf(sm.Ss[r][q * 16 + cc] - m_new);
                sm.Ss[r][q * 16 + cc] = p;
                ssum += p;
            }
            ssum += __shfl_xor_sync(0xffffffffu, ssum, 1);
            ssum += __shfl_xor_sync(0xffffffffu, ssum, 2);
            if (q == 0) {
                float cr = __expf(m_old - m_new);
                sm.lrow[r] = sm.lrow[r] * cr + ssum;
                sm.mrow[r] = m_new;
                sm.corr[r] = cr;
            }
        }
        __syncthreads();

#pragma unroll
        for (int i = 0; i < 4; i++) {
            float cr = sm.corr[ty * 4 + i];
            u64 crd = pk2(cr, cr);
#pragma unroll
            for (int j = 0; j < 4; j++) fmul2(o2[i][j], crd);
        }
#pragma unroll 4
        for (int c = 0; c < 64; c++) {
            ulonglong2 v0 = *(const ulonglong2*)&sm.Vs[c][tx * 8];
            ulonglong2 v1 = *(const ulonglong2*)&sm.Vs[c][tx * 8 + 4];
            u64 vp[4] = {v0.x, v0.y, v1.x, v1.y};
#pragma unroll
            for (int i = 0; i < 4; i++) {
                float p = sm.Ss[ty * 4 + i][c];
                u64 pd = pk2(p, p);
#pragma unroll
                for (int j = 0; j < 4; j++)
                    ffma2(o2[i][j], pd, vp[j]);
            }
        }
        __syncthreads();
    }

#pragma unroll
    for (int i = 0; i < 4; i++) {
        float invl = 1.f / sm.lrow[ty * 4 + i];
        float f[8];
        upk2(o2[i][0], f[0], f[1]); upk2(o2[i][1], f[2], f[3]);
        upk2(o2[i][2], f[4], f[5]); upk2(o2[i][3], f[6], f[7]);
        size_t off = (size_t)(q0 + ty * 4 + i) * HD_ + tx * 8;
        *(float4*)&Ob[off]     = make_float4(f[0] * invl, f[1] * invl,
                                             f[2] * invl, f[3] * invl);
        *(float4*)&Ob[off + 4] = make_float4(f[4] * invl, f[5] * invl,
                                             f[6] * invl, f[7] * invl);
    }
}

// ---------------------------------------------------------------------------
// O [B,H,S,hd] -> OtT [D][M]  (OtT[(h*128+d)][b*2048+s] = O[b,h,s,d])
// Tiled transpose, coalesced both sides.
// ---------------------------------------------------------------------------
__global__ void transpose_bhsd(const float* __restrict__ O, float* __restrict__ OtT)
{
    __shared__ float tile[32][33];
    const int bh = blockIdx.z;
    const int b = bh >> 4, h = bh & 15;
    const int s0 = blockIdx.y * 32;
    const int d0 = blockIdx.x * 32;
    const int tx = threadIdx.x, ty = threadIdx.y;

    const float* Ob = O + (size_t)bh * S_ * HD_;
#pragma unroll
    for (int j = 0; j < 4; j++)
        tile[ty + j * 8][tx] = Ob[(size_t)(s0 + ty + j * 8) * HD_ + d0 + tx];
    __syncthreads();
#pragma unroll
    for (int j = 0; j < 4; j++)
        OtT[(size_t)(h * HD_ + d0 + ty + j * 8) * M_ + b * S_ + s0 + tx] =
            tile[tx][ty + j * 8];
}

// ---------------------------------------------------------------------------
// Launch
// ---------------------------------------------------------------------------
extern "C" void kernel_launch(void* const* d_in, const int* in_sizes, int n_in,
                              void* d_out, int out_size)
{
    const float* x  = (const float*)d_in[0];
    const float* Wq = (const float*)d_in[1];
    const float* Wk = (const float*)d_in[2];
    const float* Wv = (const float*)d_in[3];
    const float* Wo = (const float*)d_in[4];
    float* out = (float*)d_out;
    (void)in_sizes; (void)n_in; (void)out_size;

    cudaFuncSetAttribute(gemm3, cudaFuncAttributeMaxDynamicSharedMemorySize, SMEMG);
    cudaFuncSetAttribute(flash_attn, cudaFuncAttributeMaxDynamicSharedMemorySize,
                         (int)sizeof(SmemAttn));

    init_rope<<<1, 64>>>();

    dim3 tb(32, 8);
    transpose32<<<dim3(D_ / 32, M_ / 32), tb>>>(x,  g_xT,  M_, D_);
    transpose32<<<dim3(D_ / 32, D_ / 32), tb>>>(Wq, g_wqT, D_, D_);
    transpose32<<<dim3(D_ / 32, D_ / 32), tb>>>(Wk, g_wkT, D_, D_);
    transpose32<<<dim3(D_ / 32, D_ / 32), tb>>>(Wv, g_wvT, D_, D_);
    transpose32<<<dim3(D_ / 32, D_ / 32), tb>>>(Wo, g_woT, D_, D_);

    // Fused QKV projections (z selects weight/output)
    gemm3<<<dim3(D_ / 128, M_ / 128, 3), 256, SMEMG>>>(
        g_xT, g_wqT, g_wkT, g_wvT, g_qraw, g_kraw, g_vraw, M_, D_, D_);

    rope_pack<<<TOT_ / 256, 256>>>(g_qraw, g_kraw, g_vraw, g_Q, g_K, g_V);

    flash_attn<<<dim3(S_ / 64, B_ * H_), 256, sizeof(SmemAttn)>>>(g_Q, g_K, g_V, g_O);

    transpose_bhsd<<<dim3(HD_ / 32, S_ / 32, B_ * H_), tb>>>(g_O, g_OtT);

    // Output projection
    gemm3<<<dim3(D_ / 128, M_ / 128, 1), 256, SMEMG>>>(
        g_OtT, g_woT, g_woT, g_woT, out, out, out, M_, D_, D_);
}